// round 1
// baseline (speedup 1.0000x reference)
#include <cuda_runtime.h>

// Problem constants
#define Bsz   16
#define Cc    8
#define Ss    128
#define PST   129          // padded SMEM row stride (129 % 32 == 1 -> bank = addr mod 32 tractable)
#define PLANE 16384        // S*S
#define CHVOL 131072       // C*S*S
#define BVOL  262144       // B*S*S
#define TOT   2097152      // B*C*S*S

// Scratch (device globals — no allocation allowed)
__device__ float g_u[TOT];      // state buffer between steps
__device__ float g_uc[TOT];     // coupled field
__device__ float g_cfu[BVOL];   // content factor from u   (pre-coupling)
__device__ float g_cfuc[BVOL];  // content factor from uc
__device__ float g_A1[CHVOL];   // alpha field at t
__device__ float g_B2[CHVOL];   // beta  field at t+DT/2
__device__ float g_A3[CHVOL];   // alpha field at t+DT
__device__ float g_bw[4];       // sigmoid(boundary_weights)

__device__ __forceinline__ float sigmoidf(float x) {
    return __fdividef(1.0f, 1.0f + __expf(-x));
}

// ---------------------------------------------------------------------------
// K0: time-dependent coefficient fields (C,S,S) + boundary weight sigmoids
// ---------------------------------------------------------------------------
__global__ void k_fields(const float* __restrict__ ab,  const float* __restrict__ bb,
                         const float* __restrict__ atc, const float* __restrict__ btc,
                         const float* __restrict__ atq, const float* __restrict__ btq,
                         const float* __restrict__ bwin,
                         float t1, float t2, float t3)
{
    int i = blockIdx.x * blockDim.x + threadIdx.x;
    if (blockIdx.x == 0 && threadIdx.x < 4)
        g_bw[threadIdx.x] = sigmoidf(bwin[threadIdx.x]);
    if (i < CHVOL) {
        float a0 = ab[i], a1 = atc[i], a2 = atq[i];
        g_A1[i] = __fmaf_rn(a2, t1 * t1, __fmaf_rn(a1, t1, a0));
        g_A3[i] = __fmaf_rn(a2, t3 * t3, __fmaf_rn(a1, t3, a0));
        g_B2[i] = __fmaf_rn(btq[i], t2 * t2, __fmaf_rn(btc[i], t2, bb[i]));
    }
}

// ---------------------------------------------------------------------------
// K1: channel coupling uc = K @ u  +  both content factors
// ---------------------------------------------------------------------------
__global__ void k_couple(const float* __restrict__ uin, const float* __restrict__ coup)
{
    __shared__ float K[64];
    if (threadIdx.x < 64) K[threadIdx.x] = coup[threadIdx.x];
    __syncthreads();

    int idx = blockIdx.x * blockDim.x + threadIdx.x;   // over B*S*S
    if (idx >= BVOL) return;
    int b = idx >> 14;
    int p = idx & (PLANE - 1);
    const float* ub = uin + (b << 17);

    float uv[8];
    float s1 = 0.0f;
#pragma unroll
    for (int d = 0; d < 8; ++d) {
        float v = ub[(d << 14) + p];
        uv[d] = v;
        s1 += sigmoidf(v);
    }
    g_cfu[idx] = __fmaf_rn(0.1f, s1 * 0.125f - 0.5f, 1.0f);

    float s2 = 0.0f;
#pragma unroll
    for (int c = 0; c < 8; ++c) {
        float a = 0.0f;
#pragma unroll
        for (int d = 0; d < 8; ++d) a = __fmaf_rn(K[c * 8 + d], uv[d], a);
        g_uc[(b << 17) + (c << 14) + p] = a;
        s2 += sigmoidf(a);
    }
    g_cfuc[idx] = __fmaf_rn(0.1f, s2 * 0.125f - 0.5f, 1.0f);
}

// ---------------------------------------------------------------------------
// Neumann tridiagonal solve:  x = d - L d + L^2 d,   (L v)_i = coeff_i * sten_i
//   sten_0     = w_lo*v_0 - v_1
//   sten_i     = 2 v_i - v_{i-1} - v_{i+1}
//   sten_{127} = w_hi*v_127 - v_126
// ncf holds -coeff.  F: field buffer (in/out). T: temp buffer.
// Thread owns positions pos = 32*s + ((j0 + 8*s) & 31)  (stagger -> bank-conflict-free)
// ---------------------------------------------------------------------------
template <int STRIDE>
__device__ __forceinline__ void solve_line(float* __restrict__ F, float* __restrict__ T,
                                           const float* ncf, int base, int s,
                                           float wlo, float whi)
{
    float acc[32];
#pragma unroll
    for (int j0 = 0; j0 < 32; ++j0) {
        int pos = 32 * s + ((j0 + 8 * s) & 31);
        int idx = base + pos * STRIDE;
        float ce = F[idx];
        float lo = F[idx - (pos > 0   ? STRIDE : 0)];
        float hi = F[idx + (pos < 127 ? STRIDE : 0)];
        float st = (pos == 0)   ? __fmaf_rn(wlo, ce, -hi)
                 : (pos == 127) ? __fmaf_rn(whi, ce, -lo)
                 : (2.0f * ce - lo - hi);
        float r = ncf[j0] * st;      // r1 = (-L) d
        T[idx] = r;
        acc[j0] = ce + r;            // d + r1
    }
    __syncthreads();
#pragma unroll
    for (int j0 = 0; j0 < 32; ++j0) {
        int pos = 32 * s + ((j0 + 8 * s) & 31);
        int idx = base + pos * STRIDE;
        float ce = T[idx];
        float lo = T[idx - (pos > 0   ? STRIDE : 0)];
        float hi = T[idx + (pos < 127 ? STRIDE : 0)];
        float st = (pos == 0)   ? __fmaf_rn(wlo, ce, -hi)
                 : (pos == 127) ? __fmaf_rn(whi, ce, -lo)
                 : (2.0f * ce - lo - hi);
        acc[j0] = __fmaf_rn(ncf[j0], st, acc[j0]);   // + r2 = (-L) r1
    }
    __syncthreads();
#pragma unroll
    for (int j0 = 0; j0 < 32; ++j0) {
        int pos = 32 * s + ((j0 + 8 * s) & 31);
        F[base + pos * STRIDE] = acc[j0];
    }
    __syncthreads();
}

// ---------------------------------------------------------------------------
// K2: one CTA per (b,c) plane: x-solve, y-solve, x-solve entirely in SMEM
// ---------------------------------------------------------------------------
__global__ __launch_bounds__(512, 1) void k_solve(float* __restrict__ out)
{
    extern __shared__ float sm[];
    float* P = sm;                 // working plane, padded rows
    float* Q = sm + Ss * PST;      // temp plane
    int bc = blockIdx.x;
    int b  = bc >> 3;
    int c  = bc & 7;
    int t  = threadIdx.x;
    int own = t >> 2;              // row (x-phase) / column (y-phase)
    int s   = t & 3;               // 32-element segment within the line

    // load uc plane (coalesced)
    const float* src = g_uc + (bc << 14);
    for (int i = t; i < Ss * Ss; i += 512)
        P[(i >> 7) * PST + (i & 127)] = src[i];

    float wl  = g_bw[3], wr  = g_bw[1];   // x: lo=left(bw3), hi=right(bw1)
    float wtp = g_bw[0], wbt = g_bw[2];   // y: lo=top(bw0),  hi=bottom(bw2)
    __syncthreads();

    float ncf[32];

    // ---- X sweep #1: alpha(t1) * cf(u),  coeff = alpha * DT/2 ----
    {
        const float* F = g_A1  + (c << 14) + (own << 7);
        const float* G = g_cfu + (b << 14) + (own << 7);
#pragma unroll
        for (int j0 = 0; j0 < 32; ++j0) {
            int w = 32 * s + ((j0 + 8 * s) & 31);
            float a = F[w] * G[w];
            a = fminf(fmaxf(a, 1e-6f), 5.0f);
            ncf[j0] = -5e-4f * a;
        }
        solve_line<1>(P, Q, ncf, own * PST, s, wl, wr);
    }

    // ---- Y sweep: beta(t2) * cf(uc),  coeff = beta * DT ----
    {
        const float* F = g_B2   + (c << 14);
        const float* G = g_cfuc + (b << 14);
#pragma unroll
        for (int j0 = 0; j0 < 32; ++j0) {
            int h = 32 * s + ((j0 + 8 * s) & 31);
            float a = F[(h << 7) + own] * G[(h << 7) + own];
            a = fminf(fmaxf(a, 1e-6f), 5.0f);
            ncf[j0] = -1e-3f * a;
        }
        solve_line<PST>(P, Q, ncf, own, s, wtp, wbt);
    }

    // ---- X sweep #2: alpha(t3) * cf(uc) ----
    {
        const float* F = g_A3   + (c << 14) + (own << 7);
        const float* G = g_cfuc + (b << 14) + (own << 7);
#pragma unroll
        for (int j0 = 0; j0 < 32; ++j0) {
            int w = 32 * s + ((j0 + 8 * s) & 31);
            float a = F[w] * G[w];
            a = fminf(fmaxf(a, 1e-6f), 5.0f);
            ncf[j0] = -5e-4f * a;
        }
        solve_line<1>(P, Q, ncf, own * PST, s, wl, wr);
    }

    // store plane (coalesced)
    float* dst = out + (bc << 14);
    for (int i = t; i < Ss * Ss; i += 512)
        dst[i] = P[(i >> 7) * PST + (i & 127)];
}

// ---------------------------------------------------------------------------
extern "C" void kernel_launch(void* const* d_in, const int* in_sizes, int n_in,
                              void* d_out, int out_size)
{
    const float* u    = (const float*)d_in[0];
    const float* ab   = (const float*)d_in[1];
    const float* bb   = (const float*)d_in[2];
    const float* atc  = (const float*)d_in[3];
    const float* btc  = (const float*)d_in[4];
    const float* atq  = (const float*)d_in[5];
    const float* btq  = (const float*)d_in[6];
    const float* coup = (const float*)d_in[7];
    const float* bw   = (const float*)d_in[8];
    float* outp = (float*)d_out;

    void* pu = nullptr;
    cudaGetSymbolAddress(&pu, g_u);
    float* gu = (float*)pu;

    const int smem = 2 * Ss * PST * (int)sizeof(float);   // 132096 bytes
    cudaFuncSetAttribute(k_solve, cudaFuncAttributeMaxDynamicSharedMemorySize, smem);

    const double DT = 0.001;
    for (int k = 0; k < 10; ++k) {
        float t1 = (float)(DT * k);
        float t2 = (float)(DT * k + 0.5 * DT);
        float t3 = (float)(DT * (k + 1));
        k_fields<<<(CHVOL + 255) / 256, 256>>>(ab, bb, atc, btc, atq, btq, bw, t1, t2, t3);
        k_couple<<<BVOL / 256, 256>>>(k == 0 ? u : gu, coup);
        k_solve<<<Bsz * Cc, 512, smem>>>(k == 9 ? outp : gu);
    }
}

// round 2
// speedup vs baseline: 1.3831x; 1.3831x over previous
#include <cuda_runtime.h>

// Problem constants
#define Bsz   16
#define Cc    8
#define Ss    128
#define PST   129          // padded SMEM row stride (129 % 32 == 1 -> tractable banks)
#define PLANE 16384        // S*S
#define BVOL  262144       // B*S*S
#define TOT   2097152      // B*C*S*S

// Scratch (device globals — no allocation allowed)
__device__ float g_u[TOT];               // state buffer between steps
__device__ float g_uc[TOT];              // coupled field
__device__ float g_Ax[11 * 8 * PLANE];   // x-permuted alpha at t = k*DT, k=0..10
__device__ float g_By[10 * 8 * PLANE];   // y-permuted beta  at t = (k+0.5)*DT
__device__ float g_cfux[Bsz * PLANE];    // x-permuted content factor from u
__device__ float g_cfucx[Bsz * PLANE];   // x-permuted content factor from uc
__device__ float g_cfucy[Bsz * PLANE];   // y-permuted content factor from uc

__device__ __forceinline__ float sigmoidf(float x) {
    return __fdividef(1.0f, 1.0f + __expf(-x));
}

// ---------------------------------------------------------------------------
// K_PREP (once): evaluate time-dependent fields for ALL steps and store them
// permuted into the exact [j0*512 + t] order k_solve consumes.
//   x-perm: value at pixel (own = t>>2, pos = 32s + ((j0+8s)&31)), s = t&3
//   y-perm: value at pixel (pos, own)
// Staged through padded SMEM so both read and write sides are conflict-free /
// coalesced.
// ---------------------------------------------------------------------------
__global__ void k_prep(const float* __restrict__ ab,  const float* __restrict__ atc,
                       const float* __restrict__ atq, const float* __restrict__ bb,
                       const float* __restrict__ btc, const float* __restrict__ btq)
{
    extern __shared__ float sm[];
    int bi = blockIdx.x;
    bool isx = bi < 88;                 // 11*8 alpha planes, then 10*8 beta planes
    int rel = isx ? bi : bi - 88;
    int k = rel >> 3;
    int c = rel & 7;
    float t = isx ? 0.001f * (float)k : 0.001f * ((float)k + 0.5f);

    const float* p0 = (isx ? ab  : bb)  + (c << 14);
    const float* p1 = (isx ? atc : btc) + (c << 14);
    const float* p2 = (isx ? atq : btq) + (c << 14);

    for (int i = threadIdx.x; i < PLANE; i += blockDim.x) {
        float v = __fmaf_rn(p2[i], t * t, __fmaf_rn(p1[i], t, p0[i]));
        sm[(i >> 7) * PST + (i & 127)] = v;
    }
    __syncthreads();

    float* out = (isx ? g_Ax : g_By) + (rel << 14);
    for (int o = threadIdx.x; o < PLANE; o += blockDim.x) {
        int tt  = o & 511;
        int j0  = o >> 9;
        int own = tt >> 2;
        int s   = tt & 3;
        int pos = 32 * s + ((j0 + 8 * s) & 31);
        out[o] = isx ? sm[own * PST + pos] : sm[pos * PST + own];
    }
}

// ---------------------------------------------------------------------------
// K_COUPLE: uc = K @ u, plus both content factors written PERMUTED.
// ---------------------------------------------------------------------------
__global__ void k_couple(const float* __restrict__ uin, const float* __restrict__ coup)
{
    __shared__ float K[64];
    if (threadIdx.x < 64) K[threadIdx.x] = coup[threadIdx.x];
    __syncthreads();

    int idx = blockIdx.x * blockDim.x + threadIdx.x;   // over B*S*S
    if (idx >= BVOL) return;
    int b = idx >> 14;
    int p = idx & (PLANE - 1);
    int r = p >> 7;
    int cc = p & 127;
    const float* ub = uin + (b << 17);

    float uv[8];
    float s1 = 0.0f;
#pragma unroll
    for (int d = 0; d < 8; ++d) {
        float v = ub[(d << 14) + p];
        uv[d] = v;
        s1 += sigmoidf(v);
    }
    // permuted indices
    int sx = cc >> 5;
    int jx = ((cc & 31) - 8 * sx) & 31;
    int ox = (b << 14) + jx * 512 + 4 * r + sx;
    int sy = r >> 5;
    int jy = ((r & 31) - 8 * sy) & 31;
    int oy = (b << 14) + jy * 512 + 4 * cc + sy;

    g_cfux[ox] = __fmaf_rn(0.1f, s1 * 0.125f - 0.5f, 1.0f);

    float s2 = 0.0f;
#pragma unroll
    for (int c = 0; c < 8; ++c) {
        float a = 0.0f;
#pragma unroll
        for (int d = 0; d < 8; ++d) a = __fmaf_rn(K[c * 8 + d], uv[d], a);
        g_uc[(b << 17) + (c << 14) + p] = a;
        s2 += sigmoidf(a);
    }
    float cfc = __fmaf_rn(0.1f, s2 * 0.125f - 0.5f, 1.0f);
    g_cfucx[ox] = cfc;
    g_cfucy[oy] = cfc;
}

// ---------------------------------------------------------------------------
// Neumann tridiagonal solve:  x = d - L d + L^2 d,   (L v)_i = coeff_i * sten_i
//   sten_0     = w_lo*v_0 - v_1
//   sten_i     = 2 v_i - v_{i-1} - v_{i+1}
//   sten_{127} = w_hi*v_127 - v_126
// ncf holds -coeff.  F: field buffer (in/out). T: temp buffer.
// Thread owns positions pos = 32*s + ((j0 + 8*s) & 31)  (conflict-free stagger)
// ---------------------------------------------------------------------------
template <int STRIDE>
__device__ __forceinline__ void solve_line(float* __restrict__ F, float* __restrict__ T,
                                           const float* ncf, int base, int s,
                                           float wlo, float whi)
{
    float acc[32];
#pragma unroll
    for (int j0 = 0; j0 < 32; ++j0) {
        int pos = 32 * s + ((j0 + 8 * s) & 31);
        int idx = base + pos * STRIDE;
        float ce = F[idx];
        float lo = F[idx - (pos > 0   ? STRIDE : 0)];
        float hi = F[idx + (pos < 127 ? STRIDE : 0)];
        float st = (pos == 0)   ? __fmaf_rn(wlo, ce, -hi)
                 : (pos == 127) ? __fmaf_rn(whi, ce, -lo)
                 : (2.0f * ce - lo - hi);
        float r = ncf[j0] * st;      // r1 = (-L) d
        T[idx] = r;
        acc[j0] = ce + r;            // d + r1
    }
    __syncthreads();
#pragma unroll
    for (int j0 = 0; j0 < 32; ++j0) {
        int pos = 32 * s + ((j0 + 8 * s) & 31);
        int idx = base + pos * STRIDE;
        float ce = T[idx];
        float lo = T[idx - (pos > 0   ? STRIDE : 0)];
        float hi = T[idx + (pos < 127 ? STRIDE : 0)];
        float st = (pos == 0)   ? __fmaf_rn(wlo, ce, -hi)
                 : (pos == 127) ? __fmaf_rn(whi, ce, -lo)
                 : (2.0f * ce - lo - hi);
        F[idx] = __fmaf_rn(ncf[j0], st, acc[j0]);   // d + r1 + r2, written in place
    }
    __syncthreads();
}

// ---------------------------------------------------------------------------
// K_SOLVE: one CTA per (b,c) plane: x-solve, y-solve, x-solve in SMEM.
// All coefficient loads are coalesced from the permuted arrays.
// ---------------------------------------------------------------------------
__global__ __launch_bounds__(512, 1) void k_solve(const float* __restrict__ bwin,
                                                  float* __restrict__ out, int k)
{
    extern __shared__ float sm[];
    float* P = sm;                 // working plane, padded rows
    float* Q = sm + Ss * PST;      // temp plane
    int bc = blockIdx.x;
    int b  = bc >> 3;
    int c  = bc & 7;
    int t  = threadIdx.x;
    int own = t >> 2;
    int s   = t & 3;

    // load uc plane (coalesced)
    const float* src = g_uc + (bc << 14);
    for (int i = t; i < PLANE; i += 512)
        P[(i >> 7) * PST + (i & 127)] = src[i];

    float wl  = sigmoidf(bwin[3]), wr  = sigmoidf(bwin[1]);   // x: lo=left, hi=right
    float wtp = sigmoidf(bwin[0]), wbt = sigmoidf(bwin[2]);   // y: lo=top,  hi=bottom
    __syncthreads();

    float ncf[32];

    // ---- X sweep #1: alpha(t1) * cf(u),  coeff = alpha * DT/2 ----
    {
        const float* F = g_Ax   + (((k * 8 + c)) << 14);
        const float* G = g_cfux + (b << 14);
#pragma unroll
        for (int j0 = 0; j0 < 32; ++j0) {
            float a = F[j0 * 512 + t] * G[j0 * 512 + t];
            a = fminf(fmaxf(a, 1e-6f), 5.0f);
            ncf[j0] = -5e-4f * a;
        }
        solve_line<1>(P, Q, ncf, own * PST, s, wl, wr);
    }

    // ---- Y sweep: beta(t2) * cf(uc),  coeff = beta * DT ----
    {
        const float* F = g_By    + (((k * 8 + c)) << 14);
        const float* G = g_cfucy + (b << 14);
#pragma unroll
        for (int j0 = 0; j0 < 32; ++j0) {
            float a = F[j0 * 512 + t] * G[j0 * 512 + t];
            a = fminf(fmaxf(a, 1e-6f), 5.0f);
            ncf[j0] = -1e-3f * a;
        }
        solve_line<PST>(P, Q, ncf, own, s, wtp, wbt);
    }

    // ---- X sweep #2: alpha(t3) * cf(uc) ----
    {
        const float* F = g_Ax    + ((((k + 1) * 8 + c)) << 14);
        const float* G = g_cfucx + (b << 14);
#pragma unroll
        for (int j0 = 0; j0 < 32; ++j0) {
            float a = F[j0 * 512 + t] * G[j0 * 512 + t];
            a = fminf(fmaxf(a, 1e-6f), 5.0f);
            ncf[j0] = -5e-4f * a;
        }
        solve_line<1>(P, Q, ncf, own * PST, s, wl, wr);
    }

    // store plane (coalesced)
    float* dst = out + (bc << 14);
    for (int i = t; i < PLANE; i += 512)
        dst[i] = P[(i >> 7) * PST + (i & 127)];
}

// ---------------------------------------------------------------------------
extern "C" void kernel_launch(void* const* d_in, const int* in_sizes, int n_in,
                              void* d_out, int out_size)
{
    const float* u    = (const float*)d_in[0];
    const float* ab   = (const float*)d_in[1];
    const float* bb   = (const float*)d_in[2];
    const float* atc  = (const float*)d_in[3];
    const float* btc  = (const float*)d_in[4];
    const float* atq  = (const float*)d_in[5];
    const float* btq  = (const float*)d_in[6];
    const float* coup = (const float*)d_in[7];
    const float* bw   = (const float*)d_in[8];
    float* outp = (float*)d_out;

    void* pu = nullptr;
    cudaGetSymbolAddress(&pu, g_u);
    float* gu = (float*)pu;

    const int smem_solve = 2 * Ss * PST * (int)sizeof(float);   // 132096 bytes
    const int smem_prep  = Ss * PST * (int)sizeof(float);       // 66048 bytes
    cudaFuncSetAttribute(k_solve, cudaFuncAttributeMaxDynamicSharedMemorySize, smem_solve);
    cudaFuncSetAttribute(k_prep,  cudaFuncAttributeMaxDynamicSharedMemorySize, smem_prep);

    // one-time field precompute: 88 alpha planes (k=0..10) + 80 beta planes (k=0..9)
    k_prep<<<168, 512, smem_prep>>>(ab, atc, atq, bb, btc, btq);

    for (int k = 0; k < 10; ++k) {
        k_couple<<<BVOL / 256, 256>>>(k == 0 ? u : gu, coup);
        k_solve<<<Bsz * Cc, 512, smem_solve>>>(bw, k == 9 ? outp : gu, k);
    }
}

// round 3
// speedup vs baseline: 1.7757x; 1.2839x over previous
#include <cuda_runtime.h>

// Problem constants
#define Bsz   16
#define Cc    8
#define Ss    128
#define PST   129          // padded SMEM row stride (129 % 32 == 1 -> clean banks)
#define PLANE 16384        // S*S
#define BVOL  262144       // B*S*S
#define TOT   2097152      // B*C*S*S
#define NTHR  1024         // k_solve threads
#define NPOS  16           // positions per k_solve thread

// Scratch (device globals — no allocation allowed)
__device__ float g_u[TOT];               // state buffer between steps
__device__ float g_uc[TOT];              // coupled field
__device__ float g_Ax[11 * 8 * PLANE];   // x-permuted alpha at t = k*DT, k=0..10
__device__ float g_By[10 * 8 * PLANE];   // y-permuted beta  at t = (k+0.5)*DT
__device__ float g_cfx[Bsz * PLANE];     // x-permuted content factor (from uc)
__device__ float g_cfy[Bsz * PLANE];     // y-permuted content factor (from uc)

__device__ __forceinline__ float sigmoidf(float x) {
    return __fdividef(1.0f, 1.0f + __expf(-x));
}

// ---------------------------------------------------------------------------
// Permuted coefficient layout consumed by k_solve (1024 threads):
//   thread t: own = t & 127, seg s = t >> 7, positions pos = 16*s + j, j=0..15
//   array address for (j, t):  addr = j*1024 + t
//   x-perm: value at pixel (row=own, col=pos)
//   y-perm: value at pixel (row=pos, col=own)
// ---------------------------------------------------------------------------

// K_PREP (once): evaluate time-dependent fields for ALL steps, store permuted.
__global__ void k_prep(const float* __restrict__ ab,  const float* __restrict__ atc,
                       const float* __restrict__ atq, const float* __restrict__ bb,
                       const float* __restrict__ btc, const float* __restrict__ btq)
{
    extern __shared__ float sm[];
    int bi = blockIdx.x;
    bool isx = bi < 88;                 // 11*8 alpha planes, then 10*8 beta planes
    int rel = isx ? bi : bi - 88;
    int k = rel >> 3;
    int c = rel & 7;
    float t = isx ? 0.001f * (float)k : 0.001f * ((float)k + 0.5f);

    const float* p0 = (isx ? ab  : bb)  + (c << 14);
    const float* p1 = (isx ? atc : btc) + (c << 14);
    const float* p2 = (isx ? atq : btq) + (c << 14);

    for (int i = threadIdx.x; i < PLANE; i += blockDim.x) {
        float v = __fmaf_rn(p2[i], t * t, __fmaf_rn(p1[i], t, p0[i]));
        sm[(i >> 7) * PST + (i & 127)] = v;
    }
    __syncthreads();

    float* out = (isx ? g_Ax : g_By) + (rel << 14);
    for (int o = threadIdx.x; o < PLANE; o += blockDim.x) {
        int j   = o >> 10;
        int tt  = o & 1023;
        int own = tt & 127;
        int s   = tt >> 7;
        int pos = NPOS * s + j;
        out[o] = isx ? sm[own * PST + pos] : sm[pos * PST + own];
    }
}

// ---------------------------------------------------------------------------
// K_COUPLE: uc = K @ u, content factor cf(uc) written in BOTH permuted layouts
// via SMEM tile transpose (all global accesses coalesced).
// One block per (b, 32-row tile, 64-col half): grid = 16*4*2 = 128, 256 thr.
// ---------------------------------------------------------------------------
__global__ __launch_bounds__(256) void k_couple(const float* __restrict__ uin,
                                                const float* __restrict__ coup)
{
    __shared__ float K[64];
    __shared__ float cf[32 * 65];
    int tid = threadIdx.x;
    if (tid < 64) K[tid] = coup[tid];

    int blk = blockIdx.x;
    int b = blk >> 3;
    int a = (blk >> 1) & 3;      // row-tile index (32 rows)
    int h = blk & 1;             // column half (64 cols)
    int r0 = a << 5, c0 = h << 6;

    const float* ub = uin + (b << 17);
    float* ucb = g_uc + (b << 17);
    __syncthreads();

#pragma unroll
    for (int i = 0; i < 8; ++i) {
        int px = tid + 256 * i;           // 2048 pixels in tile
        int rl = px >> 6, cl = px & 63;
        int p = ((r0 + rl) << 7) + (c0 + cl);

        float uv[8];
#pragma unroll
        for (int d = 0; d < 8; ++d) uv[d] = ub[(d << 14) + p];

        float ss = 0.0f;
#pragma unroll
        for (int cc = 0; cc < 8; ++cc) {
            float acc = 0.0f;
#pragma unroll
            for (int d = 0; d < 8; ++d) acc = __fmaf_rn(K[cc * 8 + d], uv[d], acc);
            ucb[(cc << 14) + p] = acc;
            ss += sigmoidf(acc);
        }
        cf[rl * 65 + cl] = __fmaf_rn(0.1f, ss * 0.125f - 0.5f, 1.0f);
    }
    __syncthreads();

    // x-perm writes: addr = j0*1024 + r + 128*sg, sg = global cc>>4
    {
        float* ox = g_cfx + (b << 14);
        int sg0 = c0 >> 4;
#pragma unroll
        for (int i = 0; i < 8; ++i) {
            int q = tid + 256 * i;
            int rr = q & 31;
            int j0 = (q >> 5) & 15;
            int sl = q >> 9;              // 0..3
            ox[j0 * 1024 + (r0 + rr) + 128 * (sg0 + sl)] = cf[rr * 65 + 16 * sl + j0];
        }
    }
    // y-perm writes: addr = (r&15)*1024 + cc + 128*(r>>4)
    {
        float* oy = g_cfy + (b << 14);
#pragma unroll
        for (int i = 0; i < 8; ++i) {
            int q = tid + 256 * i;
            int cl = q & 63;
            int rl = q >> 6;
            int rg = r0 + rl;
            oy[(rg & 15) * 1024 + (c0 + cl) + 128 * (rg >> 4)] = cf[rl * 65 + cl];
        }
    }
}

// ---------------------------------------------------------------------------
// Neumann tridiagonal solve:  x = d - L d + L^2 d,   (L v)_i = coeff_i * sten_i
//   sten_0     = w_lo*v_0 - v_1
//   sten_i     = 2 v_i - v_{i-1} - v_{i+1}
//   sten_{127} = w_hi*v_127 - v_126
// ncf holds -coeff.  F: field buffer (in/out). T: temp buffer.
// ---------------------------------------------------------------------------
template <int STRIDE>
__device__ __forceinline__ void solve_line(float* __restrict__ F, float* __restrict__ T,
                                           const float* ncf, int own_off, int pos0,
                                           float wlo, float whi)
{
    float acc[NPOS];
#pragma unroll
    for (int j = 0; j < NPOS; ++j) {
        int pos = pos0 + j;
        int idx = own_off + pos * STRIDE;
        float ce = F[idx];
        float lo = F[idx - (pos > 0   ? STRIDE : 0)];
        float hi = F[idx + (pos < 127 ? STRIDE : 0)];
        float st = (pos == 0)   ? __fmaf_rn(wlo, ce, -hi)
                 : (pos == 127) ? __fmaf_rn(whi, ce, -lo)
                 : (2.0f * ce - lo - hi);
        float r = ncf[j] * st;      // r1 = (-L) d
        T[idx] = r;
        acc[j] = ce + r;            // d + r1
    }
    __syncthreads();
#pragma unroll
    for (int j = 0; j < NPOS; ++j) {
        int pos = pos0 + j;
        int idx = own_off + pos * STRIDE;
        float ce = T[idx];
        float lo = T[idx - (pos > 0   ? STRIDE : 0)];
        float hi = T[idx + (pos < 127 ? STRIDE : 0)];
        float st = (pos == 0)   ? __fmaf_rn(wlo, ce, -hi)
                 : (pos == 127) ? __fmaf_rn(whi, ce, -lo)
                 : (2.0f * ce - lo - hi);
        F[idx] = __fmaf_rn(ncf[j], st, acc[j]);   // d + r1 + r2 in place
    }
    __syncthreads();
}

// ---------------------------------------------------------------------------
// K_SOLVE: one CTA per (b,c) plane: x-solve, y-solve, x-solve in SMEM.
// 1024 threads; all coefficient loads coalesced from permuted arrays.
// ---------------------------------------------------------------------------
__global__ __launch_bounds__(NTHR, 1) void k_solve(const float* __restrict__ bwin,
                                                   float* __restrict__ out, int k)
{
    extern __shared__ float sm[];
    float* P = sm;                 // working plane, padded rows
    float* Q = sm + Ss * PST;      // temp plane
    int bc = blockIdx.x;
    int b  = bc >> 3;
    int c  = bc & 7;
    int t  = threadIdx.x;
    int own  = t & 127;
    int pos0 = NPOS * (t >> 7);

    // load uc plane (coalesced)
    const float* src = g_uc + (bc << 14);
    for (int i = t; i < PLANE; i += NTHR)
        P[(i >> 7) * PST + (i & 127)] = src[i];

    float wl  = sigmoidf(bwin[3]), wr  = sigmoidf(bwin[1]);   // x: lo=left, hi=right
    float wtp = sigmoidf(bwin[0]), wbt = sigmoidf(bwin[2]);   // y: lo=top,  hi=bottom
    __syncthreads();

    float ncf[NPOS];

    // ---- X sweep #1: alpha(t1) * cf(uc),  coeff = alpha * DT/2 ----
    {
        const float* F = g_Ax  + ((k * 8 + c) << 14);
        const float* G = g_cfx + (b << 14);
#pragma unroll
        for (int j = 0; j < NPOS; ++j) {
            float a = F[j * 1024 + t] * G[j * 1024 + t];
            a = fminf(fmaxf(a, 1e-6f), 5.0f);
            ncf[j] = -5e-4f * a;
        }
        solve_line<1>(P, Q, ncf, own * PST, pos0, wl, wr);
    }

    // ---- Y sweep: beta(t2) * cf(uc),  coeff = beta * DT ----
    {
        const float* F = g_By  + ((k * 8 + c) << 14);
        const float* G = g_cfy + (b << 14);
#pragma unroll
        for (int j = 0; j < NPOS; ++j) {
            float a = F[j * 1024 + t] * G[j * 1024 + t];
            a = fminf(fmaxf(a, 1e-6f), 5.0f);
            ncf[j] = -1e-3f * a;
        }
        solve_line<PST>(P, Q, ncf, own, pos0, wtp, wbt);
    }

    // ---- X sweep #2: alpha(t3) * cf(uc) ----
    {
        const float* F = g_Ax  + (((k + 1) * 8 + c) << 14);
        const float* G = g_cfx + (b << 14);
#pragma unroll
        for (int j = 0; j < NPOS; ++j) {
            float a = F[j * 1024 + t] * G[j * 1024 + t];
            a = fminf(fmaxf(a, 1e-6f), 5.0f);
            ncf[j] = -5e-4f * a;
        }
        solve_line<1>(P, Q, ncf, own * PST, pos0, wl, wr);
    }

    // store plane (coalesced)
    float* dst = out + (bc << 14);
    for (int i = t; i < PLANE; i += NTHR)
        dst[i] = P[(i >> 7) * PST + (i & 127)];
}

// ---------------------------------------------------------------------------
extern "C" void kernel_launch(void* const* d_in, const int* in_sizes, int n_in,
                              void* d_out, int out_size)
{
    const float* u    = (const float*)d_in[0];
    const float* ab   = (const float*)d_in[1];
    const float* bb   = (const float*)d_in[2];
    const float* atc  = (const float*)d_in[3];
    const float* btc  = (const float*)d_in[4];
    const float* atq  = (const float*)d_in[5];
    const float* btq  = (const float*)d_in[6];
    const float* coup = (const float*)d_in[7];
    const float* bw   = (const float*)d_in[8];
    float* outp = (float*)d_out;

    void* pu = nullptr;
    cudaGetSymbolAddress(&pu, g_u);
    float* gu = (float*)pu;

    const int smem_solve = 2 * Ss * PST * (int)sizeof(float);   // 132096 bytes
    const int smem_prep  = Ss * PST * (int)sizeof(float);       // 66048 bytes
    cudaFuncSetAttribute(k_solve, cudaFuncAttributeMaxDynamicSharedMemorySize, smem_solve);
    cudaFuncSetAttribute(k_prep,  cudaFuncAttributeMaxDynamicSharedMemorySize, smem_prep);

    // one-time field precompute: 88 alpha planes (k=0..10) + 80 beta planes (k=0..9)
    k_prep<<<168, 512, smem_prep>>>(ab, atc, atq, bb, btc, btq);

    for (int k = 0; k < 10; ++k) {
        k_couple<<<128, 256>>>(k == 0 ? u : gu, coup);
        k_solve<<<Bsz * Cc, NTHR, smem_solve>>>(bw, k == 9 ? outp : gu, k);
    }
}